// round 12
// baseline (speedup 1.0000x reference)
#include <cuda_runtime.h>
#include <cuda_bf16.h>
#include <cstdint>

// Shapes fixed by setup_inputs: L=4, B=8, C=256, H=64, W=64
#define L_DIM 4
#define B_DIM 8
#define C_DIM 256
#define SPATIAL 4096
#define S4 (SPATIAL / 4)                 // 1024 float4 per slab
#define SLABS_PER_B (L_DIM * C_DIM)      // 1024 slabs per batch
#define BPG 128                          // blocks per pair-group
#define NGROUPS 4                        // 4 groups x 2 batches = 8 batches
#define GRID_X (NGROUPS * BPG)           // 512 blocks (<= 592 resident @ 4/SM)
#define NTHR 256
#define INV_SPATIAL (1.0f / 4096.0f)

// Cross-block state (allocation-free rule -> __device__ globals, zero-init).
__device__ float    g_gap[B_DIM][SLABS_PER_B];
__device__ unsigned g_done[B_DIM];
__device__ unsigned g_exit_count;

__global__ __launch_bounds__(NTHR, 4) void sffm_fused(const float* __restrict__ in,
                                                      const float* __restrict__ Wm,
                                                      float* __restrict__ out) {
    const int bid  = blockIdx.x;
    const int grp  = bid >> 7;           // pair-group 0..3
    const int j    = bid & 127;          // block within group
    const int t    = threadIdx.x;
    const int lane = t & 31;
    const int warp = t >> 5;             // 0..7; warp w handles slab 8j+w in ph2/3

    const int l  = j >> 5;               // layer of this block's 8 slabs
    const int c0 = (8 * j) & 255;        // first channel (8j..8j+7 same l)

    __shared__ float gap_sm[2][L_DIM * C_DIM];  // per-batch staged gap (8 KB)
    __shared__ float ws[2][8][8];               // per-batch reduce scratch

    const float4* in4  = (const float4*)in;
    float4*       out4 = (float4*)out;

    // ================= Phase 1: GAP for both batches, pipelined =================
#pragma unroll
    for (int ph = 0; ph < 2; ph++) {
        const int b = 2 * grp + ph;
        const size_t base = ((size_t)((l * B_DIM + b) * C_DIM + c0)) * S4;
        float r[8];
#pragma unroll
        for (int k = 0; k < 8; k++) r[k] = 0.f;
#pragma unroll
        for (int p = 0; p < 4; p++) {            // 2 slabs per iter, 8 loads deep
            const size_t a0 = base + (size_t)(2 * p)     * S4;
            const size_t a1 = base + (size_t)(2 * p + 1) * S4;
            float4 v0[4], v1[4];
#pragma unroll
            for (int i = 0; i < 4; i++) v0[i] = in4[a0 + t + i * 256];
#pragma unroll
            for (int i = 0; i < 4; i++) v1[i] = in4[a1 + t + i * 256];
#pragma unroll
            for (int i = 0; i < 4; i++) {
                r[2 * p]     += (v0[i].x + v0[i].y) + (v0[i].z + v0[i].w);
                r[2 * p + 1] += (v1[i].x + v1[i].y) + (v1[i].z + v1[i].w);
            }
        }
#pragma unroll
        for (int k = 0; k < 8; k++) {
#pragma unroll
            for (int o = 16; o; o >>= 1) r[k] += __shfl_xor_sync(0xffffffffu, r[k], o);
        }
        if (lane == 0) {
#pragma unroll
            for (int k = 0; k < 8; k++) ws[ph][k][warp] = r[k];
        }
        __syncthreads();
        if (t < 8) {
            float a = 0.f;
#pragma unroll
            for (int w = 0; w < 8; w++) a += ws[ph][t][w];
            g_gap[b][8 * j + t] = a * INV_SPATIAL;
        }
        __syncthreads();
        if (t == 0) { __threadfence(); atomicAdd(&g_done[b], 1u); }
    }

    // ============== Phase 2+3 for each batch (waits are ~free) ==============
#pragma unroll
    for (int ph = 0; ph < 2; ph++) {
        const int b = 2 * grp + ph;
        // wait: batch b's GAP table complete (usually already true)
        if (t == 0) {
            while (*(volatile unsigned*)&g_done[b] < BPG) __nanosleep(64);
            __threadfence();
        }
        __syncthreads();
        // stage gap table (4 KB, L2-hot)
#pragma unroll
        for (int i = 0; i < 4; i++) gap_sm[ph][t + i * NTHR] = g_gap[b][t + i * NTHR];
        __syncthreads();

        // ---- attn for this warp's slab (8j+w): dot of W row q over gap ----
        const int q = c0 + warp;                 // channel of warp's slab
        const float4* wr = (const float4*)(Wm + (size_t)q * C_DIM);
        const float4* g4 = (const float4*)gap_sm[ph];
        float sc0 = 0.f, sc1 = 0.f, sc2 = 0.f, sc3 = 0.f;
#pragma unroll
        for (int ii = 0; ii < 2; ii++) {
            int i = lane + ii * 32;
            float4 wv = wr[i];
            float4 a0 = g4[0 * 64 + i];
            float4 a1 = g4[1 * 64 + i];
            float4 a2 = g4[2 * 64 + i];
            float4 a3 = g4[3 * 64 + i];
            sc0 += wv.x * a0.x + wv.y * a0.y + wv.z * a0.z + wv.w * a0.w;
            sc1 += wv.x * a1.x + wv.y * a1.y + wv.z * a1.z + wv.w * a1.w;
            sc2 += wv.x * a2.x + wv.y * a2.y + wv.z * a2.z + wv.w * a2.w;
            sc3 += wv.x * a3.x + wv.y * a3.y + wv.z * a3.z + wv.w * a3.w;
        }
#pragma unroll
        for (int o = 16; o; o >>= 1) {
            sc0 += __shfl_xor_sync(0xffffffffu, sc0, o);
            sc1 += __shfl_xor_sync(0xffffffffu, sc1, o);
            sc2 += __shfl_xor_sync(0xffffffffu, sc2, o);
            sc3 += __shfl_xor_sync(0xffffffffu, sc3, o);
        }
        float m  = fmaxf(fmaxf(sc0, sc1), fmaxf(sc2, sc3));
        float e0 = __expf(sc0 - m), e1 = __expf(sc1 - m);
        float e2 = __expf(sc2 - m), e3 = __expf(sc3 - m);
        float inv = 1.0f / (e0 + e1 + e2 + e3);
        float a = ((l == 0) ? e0 : (l == 1) ? e1 : (l == 2) ? e2 : e3) * inv;

        // ---- scale this warp's slab (L2-hot re-read; streaming hints) ----
        const size_t sb = ((size_t)((l * B_DIM + b) * C_DIM + q)) * S4;
#pragma unroll 8
        for (int i = 0; i < 32; i++) {
            float4 v = __ldcs(in4 + sb + lane + i * 32);
            v.x *= a; v.y *= a; v.z *= a; v.w *= a;
            __stcs(out4 + sb + lane + i * 32, v);
        }
    }

    // ---- reset cross-launch state (last block out; graph-replay safe) ----
    __syncthreads();
    if (t == 0) {
        __threadfence();
        unsigned v = atomicAdd(&g_exit_count, 1u);
        if (v == GRID_X - 1) {
#pragma unroll
            for (int i = 0; i < B_DIM; i++) g_done[i] = 0;
            __threadfence();
            g_exit_count = 0;
        }
    }
}

extern "C" void kernel_launch(void* const* d_in, const int* in_sizes, int n_in,
                              void* d_out, int out_size) {
    const float* in  = (const float*)d_in[0];   // [L,B,C,H,W]
    const float* Wm  = (const float*)d_in[1];   // [C,C]
    float*       out = (float*)d_out;           // [L,B,C,H,W]

    sffm_fused<<<GRID_X, NTHR>>>(in, Wm, out);
}